// round 14
// baseline (speedup 1.0000x reference)
#include <cuda_runtime.h>
#include <cuda_fp16.h>
#include <math.h>
#include <stdint.h>

typedef __half f16;

// ----- problem constants -----
#define BATCH   32
#define LD      512
#define LQ      32
#define EDIM    300
#define NF      4
#define DDIM    304
#define MWIN    16
#define ALPHA   0.9f
#define HID     1024
#define H2DIM   512
#define CIN     1212
#define KCTX    912           // 3*DDIM (context-only channels)
#define KP1X    960           // KCTX padded to 64
#define PPL     9
#define NSAMP   144
#define NEG_N   128
#define NLOC    145
#define NCOL    (BATCH*NLOC)  // 4640 worst case
#define NCOLP   4704
#define NTILE   64
#define NTILES  ((NCOL + NTILE - 1) / NTILE)   // 73
#define MB4     (H2DIM/64)    // 8 m-blocks in layer 4

// ----- scratch (device globals; no allocation allowed) -----
__device__ __align__(16) f16 g_W1[(size_t)HID*KP1X];   // ctx part of W1
__device__ __align__(16) f16 g_W2[(size_t)HID*HID];
__device__ __align__(16) f16 g_W3[(size_t)HID*HID];
__device__ __align__(16) f16 g_W4[(size_t)H2DIM*HID];
__device__ __align__(16) f16 g_F [(size_t)NCOLP*KP1X];
__device__ __align__(16) f16 g_H1[(size_t)NCOLP*HID];
__device__ __align__(16) f16 g_H2[(size_t)NCOLP*HID];
__device__ __align__(16) f16 g_H3[(size_t)NCOLP*HID];
__device__ __align__(16) float g_part[2*(size_t)NCOLP*HID];  // K-split partials
__device__ __align__(16) float g_qcp[4*BATCH*HID];  // q-contrib partials (4 ksegs)
__device__ __align__(16) float g_qc[BATCH*HID];     // q-contrib  W1q . qf[b]
__device__ float g_dotp[MB4*NCOLP];   // per-mblock partial W5.relu(h4)
__device__ float g_score[NCOLP];
__device__ float g_qf[BATCH*EDIM];
__device__ int   g_used[NSAMP];
__device__ int   g_slot[NSAMP];
__device__ int   g_nused;

// ============================================================
// helpers
// ============================================================
__device__ __forceinline__ uint32_t smem_u32(const void* p) {
    uint32_t a;
    asm("{ .reg .u64 t; cvta.to.shared.u64 t, %1; cvt.u32.u64 %0, t; }" : "=r"(a) : "l"(p));
    return a;
}
#define SWZ(b) ((b) ^ (((b) >> 3) & 0x70))

#define CP16(dst, src) asm volatile("cp.async.ca.shared.global [%0], [%1], 16;" :: "r"(dst), "l"(src))
#define CP_COMMIT()    asm volatile("cp.async.commit_group;" ::: "memory")
#define CP_WAIT(n)     asm volatile("cp.async.wait_group %0;" :: "n"(n) : "memory")

__device__ __forceinline__ void ldm_x4(uint32_t& r0, uint32_t& r1, uint32_t& r2,
                                       uint32_t& r3, uint32_t addr) {
    asm volatile("ldmatrix.sync.aligned.m8n8.x4.shared.b16 {%0,%1,%2,%3}, [%4];"
        : "=r"(r0), "=r"(r1), "=r"(r2), "=r"(r3) : "r"(addr));
}
__device__ __forceinline__ void mma_f16(float* d, const uint32_t* a, const uint32_t* b) {
    asm volatile("mma.sync.aligned.m16n8k16.row.col.f32.f16.f16.f32 "
        "{%0,%1,%2,%3}, {%4,%5,%6,%7}, {%8,%9}, {%0,%1,%2,%3};"
        : "+f"(d[0]), "+f"(d[1]), "+f"(d[2]), "+f"(d[3])
        : "r"(a[0]), "r"(a[1]), "r"(a[2]), "r"(a[3]), "r"(b[0]), "r"(b[1]));
}

// ============================================================
// K0: block 0: dedup rand_idx; blocks 1..32: query FOFE vector
// ============================================================
__global__ void k_prep_qf(const int* __restrict__ rand_idx,
                          const int* __restrict__ query, const float* __restrict__ emb) {
    int tid = threadIdx.x;
    if (blockIdx.x == 0) {
        __shared__ int s_cnt[NSAMP];
        for (int i = tid; i < NSAMP; i += blockDim.x) s_cnt[i] = 0;
        __syncthreads();
        for (int n = tid; n < NEG_N; n += blockDim.x) {
            int s = rand_idx[n];
            s = min(max(s, 0), NSAMP - 1);
            atomicAdd(&s_cnt[s], 1);
        }
        __syncthreads();
        if (tid == 0) {
            int u = 0;
            for (int s = 0; s < NSAMP; s++) {
                if (s_cnt[s] > 0) { g_used[u] = s; g_slot[s] = u + 1; u++; }
                else              { g_slot[s] = 0; }
            }
            g_nused = u;
        }
    } else {
        int b = blockIdx.x - 1;
        __shared__ float qw[LQ];
        __shared__ int   tok[LQ];
        if (tid < LQ) {
            float w = 1.f;
            for (int k = 0; k < LQ - 1 - tid; k++) w *= ALPHA;
            qw[tid]  = w;
            tok[tid] = query[b * LQ + tid];
        }
        __syncthreads();
        for (int e = tid; e < EDIM; e += blockDim.x) {
            float acc = 0.f;
            #pragma unroll 4
            for (int t = 0; t < LQ; t++)
                acc += qw[t] * emb[(size_t)tok[t] * EDIM + e];
            g_qf[b * EDIM + e] = acc;
        }
    }
}

// ============================================================
// K1b: q-contrib partials: qcp[seg][b][m] = sum_{k in seg} W1[m][912+k]*qf[b][k]
//   grid (HID/128, 4); each thread: one m, 32 batch accumulators.
// ============================================================
__global__ void k_qcontrib(const float* __restrict__ W1) {
    int m   = blockIdx.x * 128 + threadIdx.x;
    int ks  = blockIdx.y;                 // 0..3
    int k0  = ks * 75, k1 = k0 + 75;      // 4*75 = 300
    __shared__ float sqf[BATCH][76];
    for (int i = threadIdx.x; i < BATCH * 75; i += 128) {
        int b = i / 75, k = i % 75;
        sqf[b][k] = g_qf[b * EDIM + k0 + k];
    }
    __syncthreads();
    const float* wrow = W1 + (size_t)m * CIN + KCTX + k0;
    float acc[BATCH];
    #pragma unroll
    for (int b = 0; b < BATCH; b++) acc[b] = 0.f;
    for (int k = 0; k < k1 - k0; k++) {
        float w = wrow[k];
        #pragma unroll
        for (int b = 0; b < BATCH; b++) acc[b] += w * sqf[b][k];
    }
    #pragma unroll
    for (int b = 0; b < BATCH; b++)
        g_qcp[(ks * BATCH + b) * HID + m] = acc[b];
}
// sum the 4 partials
__global__ void k_qsum() {
    int idx = blockIdx.x * 256 + threadIdx.x;
    if (idx < BATCH * HID) {
        g_qc[idx] = g_qcp[idx] + g_qcp[BATCH*HID + idx]
                  + g_qcp[2*BATCH*HID + idx] + g_qcp[3*BATCH*HID + idx];
    }
}

// ============================================================
// K2: build COMPACT context feature matrix (fp16, 912 channels pad 960)
// ============================================================
__global__ void k_feat(const int* __restrict__ doc, const float* __restrict__ doc_f,
                       const float* __restrict__ emb,
                       const int* __restrict__ target_s, const int* __restrict__ target_e,
                       const int* __restrict__ rand_length, const int* __restrict__ rand_position) {
    int local = blockIdx.x;
    int b     = blockIdx.y;
    int nloc  = 1 + g_nused;
    if (local >= nloc) return;

    __shared__ int   stok[3][16];
    __shared__ int   spos[3][16];
    __shared__ float sw[3][16];
    __shared__ float sdf[3][4];

    int tid = threadIdx.x;

    int base_l, pos_a, ka, base_r;
    if (local == 0) {
        int ts = target_s[b], te = target_e[b];
        base_l = max(ts - 1, 0);
        pos_a  = min(max(te, 0), LD - 1);
        ka     = te - ts;
        base_r = min(te + 1, LD - 1);
    } else {
        int s  = g_used[local - 1];
        int i  = s / PPL, j = s % PPL;
        int rl = min(max(rand_length[i], 0), MWIN - 1);
        int p  = rand_position[i * PPL + j];
        p      = min(max(p, 0), LD - 1);
        pos_a  = p;
        ka     = rl;
        base_l = min(max(p - 1, 0), LD - 1);
        base_r = min(max(p + rl + 1, 0), LD - 1);
    }

    if (tid < 48) {
        int seg = tid >> 4, k = tid & 15;
        float w = 1.f;
        for (int i = 0; i < k; i++) w *= ALPHA;
        int t; bool valid;
        if (seg == 0)      { t = base_l - k; valid = (t >= 0); }
        else if (seg == 1) { t = pos_a - k; valid = (t >= 0) && (k <= ka); }
        else               { t = base_r + k; valid = (t < LD); }
        int tc = min(max(t, 0), LD - 1);
        sw[seg][k]   = valid ? w : 0.f;
        stok[seg][k] = valid ? doc[b * LD + tc] : 0;
        spos[seg][k] = tc;
    }
    __syncthreads();
    if (tid < 12) {
        int seg = tid >> 2, f = tid & 3;
        float acc = 0.f;
        #pragma unroll
        for (int k = 0; k < 16; k++)
            acc += sw[seg][k] * doc_f[((size_t)(b * LD + spos[seg][k])) * NF + f];
        sdf[seg][f] = acc;
    }
    __syncthreads();

    size_t row = (size_t)(b * nloc + local) * KP1X;
    for (int c = tid; c < KP1X; c += blockDim.x) {
        float acc = 0.f;
        if (c < KCTX) {
            int seg = (c >= 2 * DDIM) ? 2 : ((c >= DDIM) ? 1 : 0);
            int ch = c - seg * DDIM;
            if (ch < EDIM) {
                #pragma unroll
                for (int k = 0; k < 16; k++)
                    acc += sw[seg][k] * emb[(size_t)stok[seg][k] * EDIM + ch];
            } else {
                acc = sdf[seg][ch - EDIM];
            }
        }
        g_F[row + c] = __float2half(acc);
    }
}

// ============================================================
// K2b: all-weights -> fp16 (single launch; gridDim.y = weight id)
//   W1: ctx part only (row stride CIN, K=912 pad 960)
// ============================================================
__global__ void k_conv4(const float* __restrict__ Wa, const float* __restrict__ Wb,
                        const float* __restrict__ Wc, const float* __restrict__ Wd,
                        f16* __restrict__ oa, f16* __restrict__ ob,
                        f16* __restrict__ oc, f16* __restrict__ od) {
    int which = blockIdx.y;
    const float* W; f16* o; int Mr, K, Kp, RS;
    if      (which == 0) { W = Wa; o = oa; Mr = HID;   K = KCTX; Kp = KP1X; RS = CIN; }
    else if (which == 1) { W = Wb; o = ob; Mr = HID;   K = HID; Kp = HID; RS = HID; }
    else if (which == 2) { W = Wc; o = oc; Mr = HID;   K = HID; Kp = HID; RS = HID; }
    else                 { W = Wd; o = od; Mr = H2DIM; K = HID; Kp = HID; RS = HID; }

    if (K == Kp) {
        int total4 = (Mr * Kp) >> 2;
        for (int v = blockIdx.x * blockDim.x + threadIdx.x; v < total4;
             v += gridDim.x * blockDim.x) {
            float4 f = *(const float4*)(W + (size_t)v * 4);
            f16 hv[4] = {__float2half(f.x), __float2half(f.y),
                         __float2half(f.z), __float2half(f.w)};
            *(uint2*)(o + (size_t)v * 4) = *(uint2*)hv;
        }
    } else {
        int total = Mr * Kp;
        for (int idx = blockIdx.x * blockDim.x + threadIdx.x; idx < total;
             idx += gridDim.x * blockDim.x) {
            int r = idx / Kp, k = idx - r * Kp;
            float v = (k < K) ? W[(size_t)r * RS + k] : 0.f;
            o[idx] = __float2half(v);
        }
    }
}

// ============================================================
// K3: fp16 HMMA GEMM (R11 config: CTA 64x64, 4 warps 2Mx2N, warp 32x32,
//   3-stage cp.async, 48KB, 4 CTAs/SM). KSPLIT: 2-way K halves -> g_part.
//   else (layer 4): full K, fused W5-dot epilogue -> g_dotp.
// ============================================================
#define OFF_A 0
#define OFF_B 8192
#define STAGE_BYTES 16384
#define NSTAGE 3
#define SMEM_TOT (NSTAGE*STAGE_BYTES)   // 49152

__device__ __forceinline__ void load_tile_cp(const f16* __restrict__ G, int row0,
                                             int stride, int k0, uint32_t smd, int tid) {
    #pragma unroll
    for (int it = 0; it < 4; it++) {
        int v = tid + it * 128;
        int r = v >> 3, seg = v & 7;
        const f16* src = G + (size_t)(row0 + r) * stride + k0 + seg * 8;
        CP16(smd + SWZ(r * 128 + seg * 16), src);
    }
}

template<bool KSPLIT>
__global__ __launch_bounds__(128, 4)
void k_tgemm(const f16* __restrict__ A, const f16* __restrict__ B,
             const float* __restrict__ W5, int Mdim, int K) {
    int ncols = BATCH * (1 + g_nused);
    int n0 = blockIdx.y * NTILE;
    if (n0 >= ncols) return;
    int seg  = KSPLIT ? (blockIdx.x & 1) : 0;
    int mblk = KSPLIT ? (blockIdx.x >> 1) : blockIdx.x;
    int m0 = mblk * 64;

    int nch_tot = K >> 6;
    int c0, c1;
    if (KSPLIT) {
        int half = nch_tot >> 1;
        c0 = seg ? half : 0;
        c1 = seg ? nch_tot : half;
    } else { c0 = 0; c1 = nch_tot; }

    extern __shared__ __align__(128) char sm[];
    uint32_t smb = smem_u32(sm);
    int tid  = threadIdx.x;
    int wid  = tid >> 5, lane = tid & 31;
    int wm   = wid & 1;
    int wn   = wid >> 1;

    int a_row_l = lane & 15;
    int a_off_l = (lane >> 4) << 4;
    int b_n_l   = ((lane >> 4) << 3) + (lane & 7);
    int b_off_l = ((lane >> 3) & 1) << 4;

    float acc[2][4][4];
    #pragma unroll
    for (int i = 0; i < 2; i++)
        #pragma unroll
        for (int j = 0; j < 4; j++)
            #pragma unroll
            for (int q = 0; q < 4; q++) acc[i][j][q] = 0.f;

    #pragma unroll
    for (int p = 0; p < 2; p++) {
        if (c0 + p < c1) {
            uint32_t sb = smb + p * STAGE_BYTES;
            load_tile_cp(A, m0, K, (c0 + p) << 6, sb + OFF_A, tid);
            load_tile_cp(B, n0, K, (c0 + p) << 6, sb + OFF_B, tid);
            CP_COMMIT();
        }
    }

    for (int c = c0; c < c1; c++) {
        if (c + 2 < c1) {
            uint32_t sb = smb + ((c - c0 + 2) % NSTAGE) * STAGE_BYTES;
            int k0 = (c + 2) << 6;
            load_tile_cp(A, m0, K, k0, sb + OFF_A, tid);
            load_tile_cp(B, n0, K, k0, sb + OFF_B, tid);
            CP_COMMIT();
            CP_WAIT(2);
        } else if (c + 1 < c1) {
            CP_WAIT(1);
        } else {
            CP_WAIT(0);
        }
        __syncthreads();

        uint32_t sb = smb + ((c - c0) % NSTAGE) * STAGE_BYTES;
        #pragma unroll
        for (int kk = 0; kk < 4; kk++) {
            int kb = kk << 5;
            uint32_t af[2][4], bf[2][4];
            #pragma unroll
            for (int ma = 0; ma < 2; ma++) {
                uint32_t off = SWZ((wm * 32 + ma * 16 + a_row_l) * 128 + kb + a_off_l);
                ldm_x4(af[ma][0], af[ma][1], af[ma][2], af[ma][3], sb + OFF_A + off);
            }
            #pragma unroll
            for (int nb = 0; nb < 2; nb++) {
                uint32_t off = SWZ((wn * 32 + nb * 16 + b_n_l) * 128 + kb + b_off_l);
                ldm_x4(bf[nb][0], bf[nb][1], bf[nb][2], bf[nb][3], sb + OFF_B + off);
            }
            #pragma unroll
            for (int ma = 0; ma < 2; ma++) {
                #pragma unroll
                for (int na = 0; na < 4; na++) {
                    mma_f16(acc[ma][na], af[ma], &bf[na >> 1][(na & 1) * 2]);
                }
            }
        }
        __syncthreads();
    }

    if (KSPLIT) {
        float* P = g_part + (size_t)seg * NCOLP * HID;
        #pragma unroll
        for (int ma = 0; ma < 2; ma++) {
            int mrow = m0 + wm * 32 + ma * 16 + (lane >> 2);
            #pragma unroll
            for (int na = 0; na < 4; na++) {
                int nb2 = n0 + wn * 32 + na * 8 + ((lane & 3) << 1);
                #pragma unroll
                for (int q = 0; q < 4; q++) {
                    int n = nb2 + (q & 1);
                    int m = mrow + ((q >> 1) << 3);
                    if (n < ncols)
                        P[(size_t)n * Mdim + m] = acc[ma][na][q];
                }
            }
        }
    } else {
        __shared__ float sdot[NTILE];
        for (int i = tid; i < NTILE; i += 128) sdot[i] = 0.f;
        __syncthreads();
        #pragma unroll
        for (int na = 0; na < 4; na++) {
            float p0 = 0.f, p1 = 0.f;
            #pragma unroll
            for (int ma = 0; ma < 2; ma++) {
                int mb = m0 + wm * 32 + ma * 16 + (lane >> 2);
                float w5a = W5[mb], w5b = W5[mb + 8];
                p0 += fmaxf(acc[ma][na][0], 0.f) * w5a + fmaxf(acc[ma][na][2], 0.f) * w5b;
                p1 += fmaxf(acc[ma][na][1], 0.f) * w5a + fmaxf(acc[ma][na][3], 0.f) * w5b;
            }
            int ni = wn * 32 + na * 8 + ((lane & 3) << 1);
            atomicAdd(&sdot[ni], p0);
            atomicAdd(&sdot[ni + 1], p1);
        }
        __syncthreads();
        for (int i = tid; i < NTILE; i += 128) {
            int n = n0 + i;
            if (n < ncols) g_dotp[mblk * NCOLP + n] = sdot[i];
        }
    }
}

// ============================================================
// K3b: sum 2 K-split partials (+ optional per-batch q-contrib bias)
//      + ReLU + fp16 convert
// ============================================================
template<bool BIAS>
__global__ void k_act(f16* __restrict__ O) {
    int nloc = 1 + g_nused;
    int ncols = BATCH * nloc;
    int total4 = (ncols * HID) >> 2;
    const float* P0 = g_part;
    const float* P1 = g_part + (size_t)NCOLP * HID;
    for (int v = blockIdx.x * blockDim.x + threadIdx.x; v < total4;
         v += gridDim.x * blockDim.x) {
        size_t base = (size_t)v * 4;
        float4 a = *(const float4*)(P0 + base);
        float4 b = *(const float4*)(P1 + base);
        float4 q = make_float4(0.f, 0.f, 0.f, 0.f);
        if (BIAS) {
            int n = (int)(base >> 10);        // HID = 1024
            int m = (int)(base & 1023);
            int bb = n / nloc;
            q = *(const float4*)(g_qc + bb * HID + m);
        }
        f16 hv[4] = {__float2half(fmaxf(a.x + b.x + q.x, 0.f)),
                     __float2half(fmaxf(a.y + b.y + q.y, 0.f)),
                     __float2half(fmaxf(a.z + b.z + q.z, 0.f)),
                     __float2half(fmaxf(a.w + b.w + q.w, 0.f))};
        *(uint2*)(O + base) = *(uint2*)hv;
    }
}

// ============================================================
// K5: sigmoid + loss (permutation-invariant; perm_idx drops out)
// ============================================================
__global__ void k_loss(const int* __restrict__ rand_idx, float* __restrict__ out) {
    int tid = threadIdx.x;
    int nloc = 1 + g_nused;
    int ncols = BATCH * nloc;
    for (int c = tid; c < ncols; c += 256) {
        float d = 0.f;
        #pragma unroll
        for (int p = 0; p < MB4; p++) d += g_dotp[p * NCOLP + c];
        g_score[c] = 1.f / (1.f + expf(-d));
    }
    __syncthreads();
    float acc = 0.f;
    for (int idx = tid; idx < BATCH * NEG_N; idx += 256) {
        int b = idx >> 7, n = idx & 127;
        int s = rand_idx[n];
        s = min(max(s, 0), NSAMP - 1);
        int u = g_slot[s];
        float v = g_score[b * nloc + u];
        acc += v * v;
    }
    if (tid < BATCH) {
        float v = g_score[tid * nloc] - 1.f;
        acc += 128.f * v * v;
    }
    __shared__ float sh[256];
    sh[tid] = acc;
    __syncthreads();
    for (int o = 128; o; o >>= 1) {
        if (tid < o) sh[tid] += sh[tid + o];
        __syncthreads();
    }
    if (tid == 0) out[0] = sh[0];
}

// ============================================================
// launch
// ============================================================
extern "C" void kernel_launch(void* const* d_in, const int* in_sizes, int n_in,
                              void* d_out, int out_size) {
    const int*   doc       = (const int*)  d_in[0];
    const float* doc_f     = (const float*)d_in[1];
    const int*   query     = (const int*)  d_in[2];
    const int*   target_s  = (const int*)  d_in[3];
    const int*   target_e  = (const int*)  d_in[4];
    const float* emb       = (const float*)d_in[7];
    const float* W1        = (const float*)d_in[8];
    const float* W2        = (const float*)d_in[9];
    const float* W3        = (const float*)d_in[10];
    const float* W4        = (const float*)d_in[11];
    const float* W5        = (const float*)d_in[12];
    const int*   rand_len  = (const int*)  d_in[13];
    const int*   rand_pos  = (const int*)  d_in[14];
    const int*   rand_idx  = (const int*)  d_in[15];
    float* out = (float*)d_out;

    f16 *W1p,*W2p,*W3p,*W4p,*F,*H1,*H2,*H3;
    cudaGetSymbolAddress((void**)&W1p, g_W1);
    cudaGetSymbolAddress((void**)&W2p, g_W2);
    cudaGetSymbolAddress((void**)&W3p, g_W3);
    cudaGetSymbolAddress((void**)&W4p, g_W4);
    cudaGetSymbolAddress((void**)&F,   g_F);
    cudaGetSymbolAddress((void**)&H1,  g_H1);
    cudaGetSymbolAddress((void**)&H2,  g_H2);
    cudaGetSymbolAddress((void**)&H3,  g_H3);

    cudaFuncSetAttribute(k_tgemm<true>,  cudaFuncAttributeMaxDynamicSharedMemorySize, SMEM_TOT);
    cudaFuncSetAttribute(k_tgemm<false>, cudaFuncAttributeMaxDynamicSharedMemorySize, SMEM_TOT);

    k_prep_qf<<<1 + BATCH, 256>>>(rand_idx, query, emb);
    {
        dim3 gc(512, 4);
        k_conv4<<<gc, 256>>>(W1, W2, W3, W4, W1p, W2p, W3p, W4p);
    }
    {
        dim3 gq(HID / 128, 4);
        k_qcontrib<<<gq, 128>>>(W1);
        k_qsum<<<(BATCH * HID + 255) / 256, 256>>>();
    }
    {
        dim3 g(NLOC, BATCH);
        k_feat<<<g, 256>>>(doc, doc_f, emb, target_s, target_e, rand_len, rand_pos);
    }
    {
        dim3 gs(2 * HID / 64, NTILES);   // K-split layers 1-3
        dim3 g4(H2DIM / 64,   NTILES);   // fused final layer
        k_tgemm<true ><<<gs, 128, SMEM_TOT>>>(W1p, F,  (const float*)0, HID, KP1X);
        k_act<true ><<<592, 256>>>(H1);
        k_tgemm<true ><<<gs, 128, SMEM_TOT>>>(W2p, H1, (const float*)0, HID, HID);
        k_act<false><<<592, 256>>>(H2);
        k_tgemm<true ><<<gs, 128, SMEM_TOT>>>(W3p, H2, (const float*)0, HID, HID);
        k_act<false><<<592, 256>>>(H3);
        k_tgemm<false><<<g4, 128, SMEM_TOT>>>(W4p, H3, W5, H2DIM, HID);
    }
    k_loss<<<1, 256>>>(rand_idx, out);
}

// round 15
// speedup vs baseline: 1.0517x; 1.0517x over previous
#include <cuda_runtime.h>
#include <cuda_fp16.h>
#include <math.h>
#include <stdint.h>

typedef __half f16;

// ----- problem constants -----
#define BATCH   32
#define LD      512
#define LQ      32
#define EDIM    300
#define NF      4
#define DDIM    304
#define MWIN    16
#define ALPHA   0.9f
#define HID     1024
#define H2DIM   512
#define CIN     1212
#define KP1     1216          // CIN padded to 64
#define PPL     9
#define NSAMP   144
#define NEG_N   128
#define NLOC    145
#define NCOL    (BATCH*NLOC)  // 4640 worst case
#define NCOLP   4704
#define NTILE   64
#define NTILES  ((NCOL + NTILE - 1) / NTILE)   // 73
#define MB4     (H2DIM/64)    // 8 m-blocks in layer 4

// ----- scratch (device globals; no allocation allowed) -----
__device__ __align__(16) f16 g_W1[(size_t)HID*KP1];
__device__ __align__(16) f16 g_W2[(size_t)HID*HID];
__device__ __align__(16) f16 g_W3[(size_t)HID*HID];
__device__ __align__(16) f16 g_W4[(size_t)H2DIM*HID];
__device__ __align__(16) f16 g_F [(size_t)NCOLP*KP1];
__device__ __align__(16) f16 g_H1[(size_t)NCOLP*HID];
__device__ __align__(16) f16 g_H2[(size_t)NCOLP*HID];
__device__ __align__(16) f16 g_H3[(size_t)NCOLP*HID];
__device__ __align__(16) float g_part[2*(size_t)NCOLP*HID];  // K-split partials
__device__ float g_dotp[MB4*NCOLP];     // per-mblock partial W5.relu(h4)
__device__ int   g_tcnt[(HID/64)*NTILES];  // per-tile arrival counters (self-resetting)
__device__ float g_score[NCOLP];
__device__ float g_qf[BATCH*EDIM];
__device__ int   g_used[NSAMP];
__device__ int   g_slot[NSAMP];
__device__ int   g_nused;

// ============================================================
// helpers
// ============================================================
__device__ __forceinline__ uint32_t smem_u32(const void* p) {
    uint32_t a;
    asm("{ .reg .u64 t; cvta.to.shared.u64 t, %1; cvt.u32.u64 %0, t; }" : "=r"(a) : "l"(p));
    return a;
}
#define SWZ(b) ((b) ^ (((b) >> 3) & 0x70))

#define CP16(dst, src) asm volatile("cp.async.ca.shared.global [%0], [%1], 16;" :: "r"(dst), "l"(src))
#define CP_COMMIT()    asm volatile("cp.async.commit_group;" ::: "memory")
#define CP_WAIT(n)     asm volatile("cp.async.wait_group %0;" :: "n"(n) : "memory")

__device__ __forceinline__ void ldm_x4(uint32_t& r0, uint32_t& r1, uint32_t& r2,
                                       uint32_t& r3, uint32_t addr) {
    asm volatile("ldmatrix.sync.aligned.m8n8.x4.shared.b16 {%0,%1,%2,%3}, [%4];"
        : "=r"(r0), "=r"(r1), "=r"(r2), "=r"(r3) : "r"(addr));
}
__device__ __forceinline__ void mma_f16(float* d, const uint32_t* a, const uint32_t* b) {
    asm volatile("mma.sync.aligned.m16n8k16.row.col.f32.f16.f16.f32 "
        "{%0,%1,%2,%3}, {%4,%5,%6,%7}, {%8,%9}, {%0,%1,%2,%3};"
        : "+f"(d[0]), "+f"(d[1]), "+f"(d[2]), "+f"(d[3])
        : "r"(a[0]), "r"(a[1]), "r"(a[2]), "r"(a[3]), "r"(b[0]), "r"(b[1]));
}

// ============================================================
// K0: block 0: dedup rand_idx; blocks 1..32: query FOFE vector
// ============================================================
__global__ void k_prep_qf(const int* __restrict__ rand_idx,
                          const int* __restrict__ query, const float* __restrict__ emb) {
    int tid = threadIdx.x;
    if (blockIdx.x == 0) {
        __shared__ int s_cnt[NSAMP];
        for (int i = tid; i < NSAMP; i += blockDim.x) s_cnt[i] = 0;
        __syncthreads();
        for (int n = tid; n < NEG_N; n += blockDim.x) {
            int s = rand_idx[n];
            s = min(max(s, 0), NSAMP - 1);
            atomicAdd(&s_cnt[s], 1);
        }
        __syncthreads();
        if (tid == 0) {
            int u = 0;
            for (int s = 0; s < NSAMP; s++) {
                if (s_cnt[s] > 0) { g_used[u] = s; g_slot[s] = u + 1; u++; }
                else              { g_slot[s] = 0; }
            }
            g_nused = u;
        }
    } else {
        int b = blockIdx.x - 1;
        __shared__ float qw[LQ];
        __shared__ int   tok[LQ];
        if (tid < LQ) {
            float w = 1.f;
            for (int k = 0; k < LQ - 1 - tid; k++) w *= ALPHA;
            qw[tid]  = w;
            tok[tid] = query[b * LQ + tid];
        }
        __syncthreads();
        for (int e = tid; e < EDIM; e += blockDim.x) {
            float acc = 0.f;
            #pragma unroll 4
            for (int t = 0; t < LQ; t++)
                acc += qw[t] * emb[(size_t)tok[t] * EDIM + e];
            g_qf[b * EDIM + e] = acc;
        }
    }
}

// ============================================================
// K2: build COMPACT feature matrix (fp16, K padded to KP1)
// ============================================================
__global__ void k_feat(const int* __restrict__ doc, const float* __restrict__ doc_f,
                       const float* __restrict__ emb,
                       const int* __restrict__ target_s, const int* __restrict__ target_e,
                       const int* __restrict__ rand_length, const int* __restrict__ rand_position) {
    int local = blockIdx.x;
    int b     = blockIdx.y;
    int nloc  = 1 + g_nused;
    if (local >= nloc) return;

    __shared__ int   stok[3][16];
    __shared__ int   spos[3][16];
    __shared__ float sw[3][16];
    __shared__ float sdf[3][4];

    int tid = threadIdx.x;

    int base_l, pos_a, ka, base_r;
    if (local == 0) {
        int ts = target_s[b], te = target_e[b];
        base_l = max(ts - 1, 0);
        pos_a  = min(max(te, 0), LD - 1);
        ka     = te - ts;
        base_r = min(te + 1, LD - 1);
    } else {
        int s  = g_used[local - 1];
        int i  = s / PPL, j = s % PPL;
        int rl = min(max(rand_length[i], 0), MWIN - 1);
        int p  = rand_position[i * PPL + j];
        p      = min(max(p, 0), LD - 1);
        pos_a  = p;
        ka     = rl;
        base_l = min(max(p - 1, 0), LD - 1);
        base_r = min(max(p + rl + 1, 0), LD - 1);
    }

    if (tid < 48) {
        int seg = tid >> 4, k = tid & 15;
        float w = 1.f;
        for (int i = 0; i < k; i++) w *= ALPHA;
        int t; bool valid;
        if (seg == 0)      { t = base_l - k; valid = (t >= 0); }
        else if (seg == 1) { t = pos_a - k; valid = (t >= 0) && (k <= ka); }
        else               { t = base_r + k; valid = (t < LD); }
        int tc = min(max(t, 0), LD - 1);
        sw[seg][k]   = valid ? w : 0.f;
        stok[seg][k] = valid ? doc[b * LD + tc] : 0;
        spos[seg][k] = tc;
    }
    __syncthreads();
    if (tid < 12) {
        int seg = tid >> 2, f = tid & 3;
        float acc = 0.f;
        #pragma unroll
        for (int k = 0; k < 16; k++)
            acc += sw[seg][k] * doc_f[((size_t)(b * LD + spos[seg][k])) * NF + f];
        sdf[seg][f] = acc;
    }
    __syncthreads();

    size_t row = (size_t)(b * nloc + local) * KP1;
    for (int c = tid; c < KP1; c += blockDim.x) {
        float acc = 0.f;
        if (c < 3 * DDIM) {
            int seg = (c >= 2 * DDIM) ? 2 : ((c >= DDIM) ? 1 : 0);
            int ch = c - seg * DDIM;
            if (ch < EDIM) {
                #pragma unroll
                for (int k = 0; k < 16; k++)
                    acc += sw[seg][k] * emb[(size_t)stok[seg][k] * EDIM + ch];
            } else {
                acc = sdf[seg][ch - EDIM];
            }
        } else if (c < CIN) {
            acc = g_qf[b * EDIM + (c - 3 * DDIM)];
        }
        g_F[row + c] = __float2half(acc);
    }
}

// ============================================================
// K2b: all-weights -> fp16 (single launch; gridDim.y = weight id)
// ============================================================
__global__ void k_conv4(const float* __restrict__ Wa, const float* __restrict__ Wb,
                        const float* __restrict__ Wc, const float* __restrict__ Wd,
                        f16* __restrict__ oa, f16* __restrict__ ob,
                        f16* __restrict__ oc, f16* __restrict__ od) {
    int which = blockIdx.y;
    const float* W; f16* o; int Mr, K, Kp;
    if      (which == 0) { W = Wa; o = oa; Mr = HID;   K = CIN; Kp = KP1; }
    else if (which == 1) { W = Wb; o = ob; Mr = HID;   K = HID; Kp = HID; }
    else if (which == 2) { W = Wc; o = oc; Mr = HID;   K = HID; Kp = HID; }
    else                 { W = Wd; o = od; Mr = H2DIM; K = HID; Kp = HID; }

    if (K == Kp) {
        int total4 = (Mr * Kp) >> 2;
        for (int v = blockIdx.x * blockDim.x + threadIdx.x; v < total4;
             v += gridDim.x * blockDim.x) {
            float4 f = *(const float4*)(W + (size_t)v * 4);
            f16 hv[4] = {__float2half(f.x), __float2half(f.y),
                         __float2half(f.z), __float2half(f.w)};
            *(uint2*)(o + (size_t)v * 4) = *(uint2*)hv;
        }
    } else {
        int total = Mr * Kp;
        for (int idx = blockIdx.x * blockDim.x + threadIdx.x; idx < total;
             idx += gridDim.x * blockDim.x) {
            int r = idx / Kp, k = idx - r * Kp;
            float v = (k < K) ? W[(size_t)r * K + k] : 0.f;
            o[idx] = __float2half(v);
        }
    }
}

// ============================================================
// K3: fp16 HMMA GEMM (CTA 64x64, 4 warps 2Mx2N, warp 32x32,
//   3-stage cp.async, 48KB, 4 CTAs/SM).
//   KSPLIT: 2-way K halves; last-arriving CTA of each (m,n) tile combines
//   partials in-register (ReLU+fp16) -> O. No separate k_act launch.
//   !KSPLIT (layer 4): full K, fused W5-dot epilogue -> g_dotp.
// ============================================================
#define OFF_A 0
#define OFF_B 8192
#define STAGE_BYTES 16384
#define NSTAGE 3
#define SMEM_TOT (NSTAGE*STAGE_BYTES)   // 49152

__device__ __forceinline__ void load_tile_cp(const f16* __restrict__ G, int row0,
                                             int stride, int k0, uint32_t smd, int tid) {
    #pragma unroll
    for (int it = 0; it < 4; it++) {
        int v = tid + it * 128;
        int r = v >> 3, seg = v & 7;
        const f16* src = G + (size_t)(row0 + r) * stride + k0 + seg * 8;
        CP16(smd + SWZ(r * 128 + seg * 16), src);
    }
}

template<bool KSPLIT>
__global__ __launch_bounds__(128, 4)
void k_tgemm(const f16* __restrict__ A, const f16* __restrict__ B,
             f16* __restrict__ O, const float* __restrict__ W5, int Mdim, int K) {
    int ncols = BATCH * (1 + g_nused);
    int n0 = blockIdx.y * NTILE;
    if (n0 >= ncols) return;
    int seg  = KSPLIT ? (blockIdx.x & 1) : 0;
    int mblk = KSPLIT ? (blockIdx.x >> 1) : blockIdx.x;
    int m0 = mblk * 64;

    int nch_tot = K >> 6;
    int c0, c1;
    if (KSPLIT) {
        int half = nch_tot >> 1;
        c0 = seg ? half : 0;
        c1 = seg ? nch_tot : half;
    } else { c0 = 0; c1 = nch_tot; }

    extern __shared__ __align__(128) char sm[];
    uint32_t smb = smem_u32(sm);
    int tid  = threadIdx.x;
    int wid  = tid >> 5, lane = tid & 31;
    int wm   = wid & 1;
    int wn   = wid >> 1;

    int a_row_l = lane & 15;
    int a_off_l = (lane >> 4) << 4;
    int b_n_l   = ((lane >> 4) << 3) + (lane & 7);
    int b_off_l = ((lane >> 3) & 1) << 4;

    float acc[2][4][4];
    #pragma unroll
    for (int i = 0; i < 2; i++)
        #pragma unroll
        for (int j = 0; j < 4; j++)
            #pragma unroll
            for (int q = 0; q < 4; q++) acc[i][j][q] = 0.f;

    #pragma unroll
    for (int p = 0; p < 2; p++) {
        if (c0 + p < c1) {
            uint32_t sb = smb + p * STAGE_BYTES;
            load_tile_cp(A, m0, K, (c0 + p) << 6, sb + OFF_A, tid);
            load_tile_cp(B, n0, K, (c0 + p) << 6, sb + OFF_B, tid);
            CP_COMMIT();
        }
    }

    for (int c = c0; c < c1; c++) {
        if (c + 2 < c1) {
            uint32_t sb = smb + ((c - c0 + 2) % NSTAGE) * STAGE_BYTES;
            int k0 = (c + 2) << 6;
            load_tile_cp(A, m0, K, k0, sb + OFF_A, tid);
            load_tile_cp(B, n0, K, k0, sb + OFF_B, tid);
            CP_COMMIT();
            CP_WAIT(2);
        } else if (c + 1 < c1) {
            CP_WAIT(1);
        } else {
            CP_WAIT(0);
        }
        __syncthreads();

        uint32_t sb = smb + ((c - c0) % NSTAGE) * STAGE_BYTES;
        #pragma unroll
        for (int kk = 0; kk < 4; kk++) {
            int kb = kk << 5;
            uint32_t af[2][4], bf[2][4];
            #pragma unroll
            for (int ma = 0; ma < 2; ma++) {
                uint32_t off = SWZ((wm * 32 + ma * 16 + a_row_l) * 128 + kb + a_off_l);
                ldm_x4(af[ma][0], af[ma][1], af[ma][2], af[ma][3], sb + OFF_A + off);
            }
            #pragma unroll
            for (int nb = 0; nb < 2; nb++) {
                uint32_t off = SWZ((wn * 32 + nb * 16 + b_n_l) * 128 + kb + b_off_l);
                ldm_x4(bf[nb][0], bf[nb][1], bf[nb][2], bf[nb][3], sb + OFF_B + off);
            }
            #pragma unroll
            for (int ma = 0; ma < 2; ma++) {
                #pragma unroll
                for (int na = 0; na < 4; na++) {
                    mma_f16(acc[ma][na], af[ma], &bf[na >> 1][(na & 1) * 2]);
                }
            }
        }
        __syncthreads();
    }

    if (KSPLIT) {
        // 1) publish my fp32 partial
        float* P = g_part + (size_t)seg * NCOLP * HID;
        #pragma unroll
        for (int ma = 0; ma < 2; ma++) {
            int mrow = m0 + wm * 32 + ma * 16 + (lane >> 2);
            #pragma unroll
            for (int na = 0; na < 4; na++) {
                int nb2 = n0 + wn * 32 + na * 8 + ((lane & 3) << 1);
                #pragma unroll
                for (int q = 0; q < 4; q++) {
                    int n = nb2 + (q & 1);
                    int m = mrow + ((q >> 1) << 3);
                    if (n < ncols)
                        P[(size_t)n * Mdim + m] = acc[ma][na][q];
                }
            }
        }
        __threadfence();
        // 2) arrive; last CTA of the pair combines
        __shared__ int s_old;
        int tidx = mblk * NTILES + blockIdx.y;
        if (tid == 0) s_old = atomicAdd(&g_tcnt[tidx], 1);
        __syncthreads();
        if (s_old == 1) {
            if (tid == 0) g_tcnt[tidx] = 0;   // self-reset for graph replay
            const float* Q = g_part + (size_t)(1 - seg) * NCOLP * HID;
            #pragma unroll
            for (int ma = 0; ma < 2; ma++) {
                int mrow = m0 + wm * 32 + ma * 16 + (lane >> 2);
                #pragma unroll
                for (int na = 0; na < 4; na++) {
                    int nb2 = n0 + wn * 32 + na * 8 + ((lane & 3) << 1);
                    #pragma unroll
                    for (int q = 0; q < 4; q++) {
                        int n = nb2 + (q & 1);
                        int m = mrow + ((q >> 1) << 3);
                        if (n < ncols) {
                            float v = acc[ma][na][q] + __ldcg(&Q[(size_t)n * Mdim + m]);
                            O[(size_t)n * Mdim + m] = __float2half(fmaxf(v, 0.f));
                        }
                    }
                }
            }
        }
    } else {
        // fused: per-column partial dot with W5 over this CTA's 64 m-rows
        __shared__ float sdot[NTILE];
        for (int i = tid; i < NTILE; i += 128) sdot[i] = 0.f;
        __syncthreads();
        #pragma unroll
        for (int na = 0; na < 4; na++) {
            float p0 = 0.f, p1 = 0.f;
            #pragma unroll
            for (int ma = 0; ma < 2; ma++) {
                int mb = m0 + wm * 32 + ma * 16 + (lane >> 2);
                float w5a = W5[mb], w5b = W5[mb + 8];
                p0 += fmaxf(acc[ma][na][0], 0.f) * w5a + fmaxf(acc[ma][na][2], 0.f) * w5b;
                p1 += fmaxf(acc[ma][na][1], 0.f) * w5a + fmaxf(acc[ma][na][3], 0.f) * w5b;
            }
            int ni = wn * 32 + na * 8 + ((lane & 3) << 1);
            atomicAdd(&sdot[ni], p0);
            atomicAdd(&sdot[ni + 1], p1);
        }
        __syncthreads();
        for (int i = tid; i < NTILE; i += 128) {
            int n = n0 + i;
            if (n < ncols) g_dotp[mblk * NCOLP + n] = sdot[i];
        }
    }
}

// ============================================================
// K5: sigmoid + loss (permutation-invariant; perm_idx drops out)
// ============================================================
__global__ void k_loss(const int* __restrict__ rand_idx, float* __restrict__ out) {
    int tid = threadIdx.x;
    int nloc = 1 + g_nused;
    int ncols = BATCH * nloc;
    for (int c = tid; c < ncols; c += 256) {
        float d = 0.f;
        #pragma unroll
        for (int p = 0; p < MB4; p++) d += g_dotp[p * NCOLP + c];
        g_score[c] = 1.f / (1.f + expf(-d));
    }
    __syncthreads();
    float acc = 0.f;
    for (int idx = tid; idx < BATCH * NEG_N; idx += 256) {
        int b = idx >> 7, n = idx & 127;
        int s = rand_idx[n];
        s = min(max(s, 0), NSAMP - 1);
        int u = g_slot[s];
        float v = g_score[b * nloc + u];
        acc += v * v;
    }
    if (tid < BATCH) {
        float v = g_score[tid * nloc] - 1.f;
        acc += 128.f * v * v;
    }
    __shared__ float sh[256];
    sh[tid] = acc;
    __syncthreads();
    for (int o = 128; o; o >>= 1) {
        if (tid < o) sh[tid] += sh[tid + o];
        __syncthreads();
    }
    if (tid == 0) out[0] = sh[0];
}

// ============================================================
// launch
// ============================================================
extern "C" void kernel_launch(void* const* d_in, const int* in_sizes, int n_in,
                              void* d_out, int out_size) {
    const int*   doc       = (const int*)  d_in[0];
    const float* doc_f     = (const float*)d_in[1];
    const int*   query     = (const int*)  d_in[2];
    const int*   target_s  = (const int*)  d_in[3];
    const int*   target_e  = (const int*)  d_in[4];
    const float* emb       = (const float*)d_in[7];
    const float* W1        = (const float*)d_in[8];
    const float* W2        = (const float*)d_in[9];
    const float* W3        = (const float*)d_in[10];
    const float* W4        = (const float*)d_in[11];
    const float* W5        = (const float*)d_in[12];
    const int*   rand_len  = (const int*)  d_in[13];
    const int*   rand_pos  = (const int*)  d_in[14];
    const int*   rand_idx  = (const int*)  d_in[15];
    float* out = (float*)d_out;

    f16 *W1p,*W2p,*W3p,*W4p,*F,*H1,*H2,*H3;
    cudaGetSymbolAddress((void**)&W1p, g_W1);
    cudaGetSymbolAddress((void**)&W2p, g_W2);
    cudaGetSymbolAddress((void**)&W3p, g_W3);
    cudaGetSymbolAddress((void**)&W4p, g_W4);
    cudaGetSymbolAddress((void**)&F,   g_F);
    cudaGetSymbolAddress((void**)&H1,  g_H1);
    cudaGetSymbolAddress((void**)&H2,  g_H2);
    cudaGetSymbolAddress((void**)&H3,  g_H3);

    cudaFuncSetAttribute(k_tgemm<true>,  cudaFuncAttributeMaxDynamicSharedMemorySize, SMEM_TOT);
    cudaFuncSetAttribute(k_tgemm<false>, cudaFuncAttributeMaxDynamicSharedMemorySize, SMEM_TOT);

    k_prep_qf<<<1 + BATCH, 256>>>(rand_idx, query, emb);
    {
        dim3 gc(512, 4);
        k_conv4<<<gc, 256>>>(W1, W2, W3, W4, W1p, W2p, W3p, W4p);
    }
    {
        dim3 g(NLOC, BATCH);
        k_feat<<<g, 256>>>(doc, doc_f, emb, target_s, target_e, rand_len, rand_pos);
    }
    {
        dim3 gs(2 * HID / 64, NTILES);   // K-split layers w/ fused combine
        dim3 g4(H2DIM / 64,   NTILES);   // fused final layer
        k_tgemm<true ><<<gs, 128, SMEM_TOT>>>(W1p, F,  H1, (const float*)0, HID, KP1);
        k_tgemm<true ><<<gs, 128, SMEM_TOT>>>(W2p, H1, H2, (const float*)0, HID, HID);
        k_tgemm<true ><<<gs, 128, SMEM_TOT>>>(W3p, H2, H3, (const float*)0, HID, HID);
        k_tgemm<false><<<g4, 128, SMEM_TOT>>>(W4p, H3, (f16*)0, W5, H2DIM, HID);
    }
    k_loss<<<1, 256>>>(rand_idx, out);
}

// round 16
// speedup vs baseline: 1.2724x; 1.2098x over previous
#include <cuda_runtime.h>
#include <cuda_fp16.h>
#include <math.h>
#include <stdint.h>

typedef __half f16;

// ----- problem constants -----
#define BATCH   32
#define LD      512
#define LQ      32
#define EDIM    300
#define NF      4
#define DDIM    304
#define MWIN    16
#define ALPHA   0.9f
#define HID     1024
#define H2DIM   512
#define CIN     1212
#define KP1     1216          // CIN padded to 64
#define PPL     9
#define NSAMP   144
#define NEG_N   128
#define NLOC    145
#define NCOL    (BATCH*NLOC)  // 4640 worst case
#define NCOLP   4704
#define NTILE   64
#define NTILES  ((NCOL + NTILE - 1) / NTILE)   // 73
#define MB4     (H2DIM/64)    // 8 m-blocks in layer 4

// ----- scratch (device globals; no allocation allowed) -----
__device__ __align__(16) f16 g_W1[(size_t)HID*KP1];
__device__ __align__(16) f16 g_W2[(size_t)HID*HID];
__device__ __align__(16) f16 g_W3[(size_t)HID*HID];
__device__ __align__(16) f16 g_W4[(size_t)H2DIM*HID];
__device__ __align__(16) f16 g_F [(size_t)NCOLP*KP1];
__device__ __align__(16) f16 g_H1[(size_t)NCOLP*HID];
__device__ __align__(16) f16 g_H2[(size_t)NCOLP*HID];
__device__ __align__(16) f16 g_H3[(size_t)NCOLP*HID];
__device__ __align__(16) float g_part[2*(size_t)NCOLP*HID];  // K-split partials
__device__ float g_dotp[MB4*NCOLP];   // per-mblock partial W5.relu(h4)
__device__ float g_score[NCOLP];
__device__ float g_qf[BATCH*EDIM];
__device__ int   g_used[NSAMP];
__device__ int   g_slot[NSAMP];
__device__ int   g_nused;

// ============================================================
// helpers
// ============================================================
__device__ __forceinline__ uint32_t smem_u32(const void* p) {
    uint32_t a;
    asm("{ .reg .u64 t; cvta.to.shared.u64 t, %1; cvt.u32.u64 %0, t; }" : "=r"(a) : "l"(p));
    return a;
}
#define SWZ(b) ((b) ^ (((b) >> 3) & 0x70))

#define CP16(dst, src) asm volatile("cp.async.ca.shared.global [%0], [%1], 16;" :: "r"(dst), "l"(src))
#define CP_COMMIT()    asm volatile("cp.async.commit_group;" ::: "memory")
#define CP_WAIT(n)     asm volatile("cp.async.wait_group %0;" :: "n"(n) : "memory")

__device__ __forceinline__ void ldm_x4(uint32_t& r0, uint32_t& r1, uint32_t& r2,
                                       uint32_t& r3, uint32_t addr) {
    asm volatile("ldmatrix.sync.aligned.m8n8.x4.shared.b16 {%0,%1,%2,%3}, [%4];"
        : "=r"(r0), "=r"(r1), "=r"(r2), "=r"(r3) : "r"(addr));
}
__device__ __forceinline__ void mma_f16(float* d, const uint32_t* a, const uint32_t* b) {
    asm volatile("mma.sync.aligned.m16n8k16.row.col.f32.f16.f16.f32 "
        "{%0,%1,%2,%3}, {%4,%5,%6,%7}, {%8,%9}, {%0,%1,%2,%3};"
        : "+f"(d[0]), "+f"(d[1]), "+f"(d[2]), "+f"(d[3])
        : "r"(a[0]), "r"(a[1]), "r"(a[2]), "r"(a[3]), "r"(b[0]), "r"(b[1]));
}

// ============================================================
// K0 (merged): block 0: dedup rand_idx; blocks 1..32: query FOFE;
//              blocks 33..: weight fp16 conversion (4 x 512 blocks).
//   All phases independent; consumers run in later kernels.
// ============================================================
#define CONV_BLKS 512
__global__ void k_pre(const int* __restrict__ rand_idx,
                      const int* __restrict__ query, const float* __restrict__ emb,
                      const float* __restrict__ Wa, const float* __restrict__ Wb,
                      const float* __restrict__ Wc, const float* __restrict__ Wd) {
    int tid = threadIdx.x;
    int bx  = blockIdx.x;
    if (bx == 0) {
        __shared__ int s_cnt[NSAMP];
        for (int i = tid; i < NSAMP; i += blockDim.x) s_cnt[i] = 0;
        __syncthreads();
        for (int n = tid; n < NEG_N; n += blockDim.x) {
            int s = rand_idx[n];
            s = min(max(s, 0), NSAMP - 1);
            atomicAdd(&s_cnt[s], 1);
        }
        __syncthreads();
        if (tid == 0) {
            int u = 0;
            for (int s = 0; s < NSAMP; s++) {
                if (s_cnt[s] > 0) { g_used[u] = s; g_slot[s] = u + 1; u++; }
                else              { g_slot[s] = 0; }
            }
            g_nused = u;
        }
    } else if (bx <= BATCH) {
        int b = bx - 1;
        __shared__ float qw[LQ];
        __shared__ int   tok[LQ];
        if (tid < LQ) {
            float w = 1.f;
            for (int k = 0; k < LQ - 1 - tid; k++) w *= ALPHA;
            qw[tid]  = w;
            tok[tid] = query[b * LQ + tid];
        }
        __syncthreads();
        for (int e = tid; e < EDIM; e += blockDim.x) {
            float acc = 0.f;
            #pragma unroll 4
            for (int t = 0; t < LQ; t++)
                acc += qw[t] * emb[(size_t)tok[t] * EDIM + e];
            g_qf[b * EDIM + e] = acc;
        }
    } else {
        int cidx  = bx - 1 - BATCH;          // 0 .. 4*CONV_BLKS-1
        int which = cidx / CONV_BLKS;
        int cb    = cidx % CONV_BLKS;
        const float* W; f16* o; int Mr, K, Kp;
        if      (which == 0) { W = Wa; o = g_W1; Mr = HID;   K = CIN; Kp = KP1; }
        else if (which == 1) { W = Wb; o = g_W2; Mr = HID;   K = HID; Kp = HID; }
        else if (which == 2) { W = Wc; o = g_W3; Mr = HID;   K = HID; Kp = HID; }
        else                 { W = Wd; o = g_W4; Mr = H2DIM; K = HID; Kp = HID; }

        if (K == Kp) {
            int total4 = (Mr * Kp) >> 2;
            for (int v = cb * blockDim.x + tid; v < total4;
                 v += CONV_BLKS * blockDim.x) {
                float4 f = *(const float4*)(W + (size_t)v * 4);
                f16 hv[4] = {__float2half(f.x), __float2half(f.y),
                             __float2half(f.z), __float2half(f.w)};
                *(uint2*)(o + (size_t)v * 4) = *(uint2*)hv;
            }
        } else {
            int total = Mr * Kp;
            for (int idx = cb * blockDim.x + tid; idx < total;
                 idx += CONV_BLKS * blockDim.x) {
                int r = idx / Kp, k = idx - r * Kp;
                float v = (k < K) ? W[(size_t)r * K + k] : 0.f;
                o[idx] = __float2half(v);
            }
        }
    }
}

// ============================================================
// K2: build COMPACT feature matrix (fp16, K padded to KP1)
// ============================================================
__global__ void k_feat(const int* __restrict__ doc, const float* __restrict__ doc_f,
                       const float* __restrict__ emb,
                       const int* __restrict__ target_s, const int* __restrict__ target_e,
                       const int* __restrict__ rand_length, const int* __restrict__ rand_position) {
    int local = blockIdx.x;
    int b     = blockIdx.y;
    int nloc  = 1 + g_nused;
    if (local >= nloc) return;

    __shared__ int   stok[3][16];
    __shared__ int   spos[3][16];
    __shared__ float sw[3][16];
    __shared__ float sdf[3][4];

    int tid = threadIdx.x;

    int base_l, pos_a, ka, base_r;
    if (local == 0) {
        int ts = target_s[b], te = target_e[b];
        base_l = max(ts - 1, 0);
        pos_a  = min(max(te, 0), LD - 1);
        ka     = te - ts;
        base_r = min(te + 1, LD - 1);
    } else {
        int s  = g_used[local - 1];
        int i  = s / PPL, j = s % PPL;
        int rl = min(max(rand_length[i], 0), MWIN - 1);
        int p  = rand_position[i * PPL + j];
        p      = min(max(p, 0), LD - 1);
        pos_a  = p;
        ka     = rl;
        base_l = min(max(p - 1, 0), LD - 1);
        base_r = min(max(p + rl + 1, 0), LD - 1);
    }

    if (tid < 48) {
        int seg = tid >> 4, k = tid & 15;
        float w = 1.f;
        for (int i = 0; i < k; i++) w *= ALPHA;
        int t; bool valid;
        if (seg == 0)      { t = base_l - k; valid = (t >= 0); }
        else if (seg == 1) { t = pos_a - k; valid = (t >= 0) && (k <= ka); }
        else               { t = base_r + k; valid = (t < LD); }
        int tc = min(max(t, 0), LD - 1);
        sw[seg][k]   = valid ? w : 0.f;
        stok[seg][k] = valid ? doc[b * LD + tc] : 0;
        spos[seg][k] = tc;
    }
    __syncthreads();
    if (tid < 12) {
        int seg = tid >> 2, f = tid & 3;
        float acc = 0.f;
        #pragma unroll
        for (int k = 0; k < 16; k++)
            acc += sw[seg][k] * doc_f[((size_t)(b * LD + spos[seg][k])) * NF + f];
        sdf[seg][f] = acc;
    }
    __syncthreads();

    size_t row = (size_t)(b * nloc + local) * KP1;
    for (int c = tid; c < KP1; c += blockDim.x) {
        float acc = 0.f;
        if (c < 3 * DDIM) {
            int seg = (c >= 2 * DDIM) ? 2 : ((c >= DDIM) ? 1 : 0);
            int ch = c - seg * DDIM;
            if (ch < EDIM) {
                #pragma unroll
                for (int k = 0; k < 16; k++)
                    acc += sw[seg][k] * emb[(size_t)stok[seg][k] * EDIM + ch];
            } else {
                acc = sdf[seg][ch - EDIM];
            }
        } else if (c < CIN) {
            acc = g_qf[b * EDIM + (c - 3 * DDIM)];
        }
        g_F[row + c] = __float2half(acc);
    }
}

// ============================================================
// K3: fp16 HMMA GEMM (R11 config: CTA 64x64, 4 warps 2Mx2N, warp 32x32,
//   3-stage cp.async, 48KB, 4 CTAs/SM). KSPLIT: 2-way K halves -> g_part.
//   !KSPLIT (layer 4): full K, fused W5-dot epilogue -> g_dotp.
// ============================================================
#define OFF_A 0
#define OFF_B 8192
#define STAGE_BYTES 16384
#define NSTAGE 3
#define SMEM_TOT (NSTAGE*STAGE_BYTES)   // 49152

__device__ __forceinline__ void load_tile_cp(const f16* __restrict__ G, int row0,
                                             int stride, int k0, uint32_t smd, int tid) {
    #pragma unroll
    for (int it = 0; it < 4; it++) {
        int v = tid + it * 128;
        int r = v >> 3, seg = v & 7;
        const f16* src = G + (size_t)(row0 + r) * stride + k0 + seg * 8;
        CP16(smd + SWZ(r * 128 + seg * 16), src);
    }
}

template<bool KSPLIT>
__global__ __launch_bounds__(128, 4)
void k_tgemm(const f16* __restrict__ A, const f16* __restrict__ B,
             const float* __restrict__ W5, int Mdim, int K) {
    int ncols = BATCH * (1 + g_nused);
    int n0 = blockIdx.y * NTILE;
    if (n0 >= ncols) return;
    int seg  = KSPLIT ? (blockIdx.x & 1) : 0;
    int mblk = KSPLIT ? (blockIdx.x >> 1) : blockIdx.x;
    int m0 = mblk * 64;

    int nch_tot = K >> 6;
    int c0, c1;
    if (KSPLIT) {
        int half = nch_tot >> 1;
        c0 = seg ? half : 0;
        c1 = seg ? nch_tot : half;
    } else { c0 = 0; c1 = nch_tot; }

    extern __shared__ __align__(128) char sm[];
    uint32_t smb = smem_u32(sm);
    int tid  = threadIdx.x;
    int wid  = tid >> 5, lane = tid & 31;
    int wm   = wid & 1;
    int wn   = wid >> 1;

    int a_row_l = lane & 15;
    int a_off_l = (lane >> 4) << 4;
    int b_n_l   = ((lane >> 4) << 3) + (lane & 7);
    int b_off_l = ((lane >> 3) & 1) << 4;

    float acc[2][4][4];
    #pragma unroll
    for (int i = 0; i < 2; i++)
        #pragma unroll
        for (int j = 0; j < 4; j++)
            #pragma unroll
            for (int q = 0; q < 4; q++) acc[i][j][q] = 0.f;

    #pragma unroll
    for (int p = 0; p < 2; p++) {
        if (c0 + p < c1) {
            uint32_t sb = smb + p * STAGE_BYTES;
            load_tile_cp(A, m0, K, (c0 + p) << 6, sb + OFF_A, tid);
            load_tile_cp(B, n0, K, (c0 + p) << 6, sb + OFF_B, tid);
            CP_COMMIT();
        }
    }

    for (int c = c0; c < c1; c++) {
        if (c + 2 < c1) {
            uint32_t sb = smb + ((c - c0 + 2) % NSTAGE) * STAGE_BYTES;
            int k0 = (c + 2) << 6;
            load_tile_cp(A, m0, K, k0, sb + OFF_A, tid);
            load_tile_cp(B, n0, K, k0, sb + OFF_B, tid);
            CP_COMMIT();
            CP_WAIT(2);
        } else if (c + 1 < c1) {
            CP_WAIT(1);
        } else {
            CP_WAIT(0);
        }
        __syncthreads();

        uint32_t sb = smb + ((c - c0) % NSTAGE) * STAGE_BYTES;
        #pragma unroll
        for (int kk = 0; kk < 4; kk++) {
            int kb = kk << 5;
            uint32_t af[2][4], bf[2][4];
            #pragma unroll
            for (int ma = 0; ma < 2; ma++) {
                uint32_t off = SWZ((wm * 32 + ma * 16 + a_row_l) * 128 + kb + a_off_l);
                ldm_x4(af[ma][0], af[ma][1], af[ma][2], af[ma][3], sb + OFF_A + off);
            }
            #pragma unroll
            for (int nb = 0; nb < 2; nb++) {
                uint32_t off = SWZ((wn * 32 + nb * 16 + b_n_l) * 128 + kb + b_off_l);
                ldm_x4(bf[nb][0], bf[nb][1], bf[nb][2], bf[nb][3], sb + OFF_B + off);
            }
            #pragma unroll
            for (int ma = 0; ma < 2; ma++) {
                #pragma unroll
                for (int na = 0; na < 4; na++) {
                    mma_f16(acc[ma][na], af[ma], &bf[na >> 1][(na & 1) * 2]);
                }
            }
        }
        __syncthreads();
    }

    if (KSPLIT) {
        float* P = g_part + (size_t)seg * NCOLP * HID;
        #pragma unroll
        for (int ma = 0; ma < 2; ma++) {
            int mrow = m0 + wm * 32 + ma * 16 + (lane >> 2);
            #pragma unroll
            for (int na = 0; na < 4; na++) {
                int nb2 = n0 + wn * 32 + na * 8 + ((lane & 3) << 1);
                #pragma unroll
                for (int q = 0; q < 4; q++) {
                    int n = nb2 + (q & 1);
                    int m = mrow + ((q >> 1) << 3);
                    if (n < ncols)
                        P[(size_t)n * Mdim + m] = acc[ma][na][q];
                }
            }
        }
    } else {
        __shared__ float sdot[NTILE];
        for (int i = tid; i < NTILE; i += 128) sdot[i] = 0.f;
        __syncthreads();
        #pragma unroll
        for (int na = 0; na < 4; na++) {
            float p0 = 0.f, p1 = 0.f;
            #pragma unroll
            for (int ma = 0; ma < 2; ma++) {
                int mb = m0 + wm * 32 + ma * 16 + (lane >> 2);
                float w5a = W5[mb], w5b = W5[mb + 8];
                p0 += fmaxf(acc[ma][na][0], 0.f) * w5a + fmaxf(acc[ma][na][2], 0.f) * w5b;
                p1 += fmaxf(acc[ma][na][1], 0.f) * w5a + fmaxf(acc[ma][na][3], 0.f) * w5b;
            }
            int ni = wn * 32 + na * 8 + ((lane & 3) << 1);
            atomicAdd(&sdot[ni], p0);
            atomicAdd(&sdot[ni + 1], p1);
        }
        __syncthreads();
        for (int i = tid; i < NTILE; i += 128) {
            int n = n0 + i;
            if (n < ncols) g_dotp[mblk * NCOLP + n] = sdot[i];
        }
    }
}

// ============================================================
// K3b: sum 2 K-split partials + ReLU + fp16 convert
// ============================================================
__global__ void k_act(f16* __restrict__ O) {
    int ncols = BATCH * (1 + g_nused);
    int total4 = (ncols * HID) >> 2;
    const float* P0 = g_part;
    const float* P1 = g_part + (size_t)NCOLP * HID;
    for (int v = blockIdx.x * blockDim.x + threadIdx.x; v < total4;
         v += gridDim.x * blockDim.x) {
        size_t base = (size_t)v * 4;
        float4 a = *(const float4*)(P0 + base);
        float4 b = *(const float4*)(P1 + base);
        f16 hv[4] = {__float2half(fmaxf(a.x + b.x, 0.f)),
                     __float2half(fmaxf(a.y + b.y, 0.f)),
                     __float2half(fmaxf(a.z + b.z, 0.f)),
                     __float2half(fmaxf(a.w + b.w, 0.f))};
        *(uint2*)(O + base) = *(uint2*)hv;
    }
}

// ============================================================
// K5: sigmoid + loss (permutation-invariant; perm_idx drops out)
// ============================================================
__global__ void k_loss(const int* __restrict__ rand_idx, float* __restrict__ out) {
    int tid = threadIdx.x;
    int nloc = 1 + g_nused;
    int ncols = BATCH * nloc;
    for (int c = tid; c < ncols; c += 256) {
        float d = 0.f;
        #pragma unroll
        for (int p = 0; p < MB4; p++) d += g_dotp[p * NCOLP + c];
        g_score[c] = 1.f / (1.f + expf(-d));
    }
    __syncthreads();
    float acc = 0.f;
    for (int idx = tid; idx < BATCH * NEG_N; idx += 256) {
        int b = idx >> 7, n = idx & 127;
        int s = rand_idx[n];
        s = min(max(s, 0), NSAMP - 1);
        int u = g_slot[s];
        float v = g_score[b * nloc + u];
        acc += v * v;
    }
    if (tid < BATCH) {
        float v = g_score[tid * nloc] - 1.f;
        acc += 128.f * v * v;
    }
    __shared__ float sh[256];
    sh[tid] = acc;
    __syncthreads();
    for (int o = 128; o; o >>= 1) {
        if (tid < o) sh[tid] += sh[tid + o];
        __syncthreads();
    }
    if (tid == 0) out[0] = sh[0];
}

// ============================================================
// launch
// ============================================================
extern "C" void kernel_launch(void* const* d_in, const int* in_sizes, int n_in,
                              void* d_out, int out_size) {
    const int*   doc       = (const int*)  d_in[0];
    const float* doc_f     = (const float*)d_in[1];
    const int*   query     = (const int*)  d_in[2];
    const int*   target_s  = (const int*)  d_in[3];
    const int*   target_e  = (const int*)  d_in[4];
    const float* emb       = (const float*)d_in[7];
    const float* W1        = (const float*)d_in[8];
    const float* W2        = (const float*)d_in[9];
    const float* W3        = (const float*)d_in[10];
    const float* W4        = (const float*)d_in[11];
    const float* W5        = (const float*)d_in[12];
    const int*   rand_len  = (const int*)  d_in[13];
    const int*   rand_pos  = (const int*)  d_in[14];
    const int*   rand_idx  = (const int*)  d_in[15];
    float* out = (float*)d_out;

    f16 *W1p,*W2p,*W3p,*W4p,*F,*H1,*H2,*H3;
    cudaGetSymbolAddress((void**)&W1p, g_W1);
    cudaGetSymbolAddress((void**)&W2p, g_W2);
    cudaGetSymbolAddress((void**)&W3p, g_W3);
    cudaGetSymbolAddress((void**)&W4p, g_W4);
    cudaGetSymbolAddress((void**)&F,   g_F);
    cudaGetSymbolAddress((void**)&H1,  g_H1);
    cudaGetSymbolAddress((void**)&H2,  g_H2);
    cudaGetSymbolAddress((void**)&H3,  g_H3);

    cudaFuncSetAttribute(k_tgemm<true>,  cudaFuncAttributeMaxDynamicSharedMemorySize, SMEM_TOT);
    cudaFuncSetAttribute(k_tgemm<false>, cudaFuncAttributeMaxDynamicSharedMemorySize, SMEM_TOT);

    // merged: dedup + query-FOFE + weight conversion (independent phases)
    k_pre<<<1 + BATCH + 4 * CONV_BLKS, 256>>>(rand_idx, query, emb, W1, W2, W3, W4);
    {
        dim3 g(NLOC, BATCH);
        k_feat<<<g, 256>>>(doc, doc_f, emb, target_s, target_e, rand_len, rand_pos);
    }
    {
        dim3 gs(2 * HID / 64, NTILES);   // K-split layers 1-3
        dim3 g4(H2DIM / 64,   NTILES);   // fused final layer
        k_tgemm<true ><<<gs, 128, SMEM_TOT>>>(W1p, F,  (const float*)0, HID, KP1);
        k_act<<<592, 256>>>(H1);
        k_tgemm<true ><<<gs, 128, SMEM_TOT>>>(W2p, H1, (const float*)0, HID, HID);
        k_act<<<592, 256>>>(H2);
        k_tgemm<true ><<<gs, 128, SMEM_TOT>>>(W3p, H2, (const float*)0, HID, HID);
        k_act<<<592, 256>>>(H3);
        k_tgemm<false><<<g4, 128, SMEM_TOT>>>(W4p, H3, W5, H2DIM, HID);
    }
    k_loss<<<1, 256>>>(rand_idx, out);
}

// round 17
// speedup vs baseline: 1.3055x; 1.0261x over previous
#include <cuda_runtime.h>
#include <cuda_fp16.h>
#include <math.h>
#include <stdint.h>

typedef __half f16;

// ----- problem constants -----
#define BATCH   32
#define LD      512
#define LQ      32
#define EDIM    300
#define NF      4
#define DDIM    304
#define MWIN    16
#define ALPHA   0.9f
#define HID     1024
#define H2DIM   512
#define CIN     1212
#define KP1     1216          // CIN padded to 64
#define PPL     9
#define NSAMP   144
#define NEG_N   128
#define NLOC    145
#define NCOL    (BATCH*NLOC)  // 4640 worst case
#define NCOLP   4704
#define NTILE   64
#define NTILES  ((NCOL + NTILE - 1) / NTILE)   // 73
#define MB4     (H2DIM/64)    // 8 m-blocks in layer 4

// ----- scratch (device globals; no allocation allowed) -----
__device__ __align__(16) f16 g_W1[(size_t)HID*KP1];
__device__ __align__(16) f16 g_W2[(size_t)HID*HID];
__device__ __align__(16) f16 g_W3[(size_t)HID*HID];
__device__ __align__(16) f16 g_W4[(size_t)H2DIM*HID];
__device__ __align__(16) f16 g_F [(size_t)NCOLP*KP1];
__device__ __align__(16) f16 g_H1[(size_t)NCOLP*HID];
__device__ __align__(16) f16 g_H2[(size_t)NCOLP*HID];
__device__ __align__(16) f16 g_H3[(size_t)NCOLP*HID];
__device__ __align__(16) f16 g_part[2*(size_t)NCOLP*HID];   // K-split partials (fp16)
__device__ float g_dotp[MB4*NCOLP];   // per-mblock partial W5.relu(h4)
__device__ float g_score[NCOLP];
__device__ float g_qf[BATCH*EDIM];
__device__ int   g_used[NSAMP];
__device__ int   g_slot[NSAMP];
__device__ int   g_nused;

// ============================================================
// helpers
// ============================================================
__device__ __forceinline__ uint32_t smem_u32(const void* p) {
    uint32_t a;
    asm("{ .reg .u64 t; cvta.to.shared.u64 t, %1; cvt.u32.u64 %0, t; }" : "=r"(a) : "l"(p));
    return a;
}
#define SWZ(b) ((b) ^ (((b) >> 3) & 0x70))

#define CP16(dst, src) asm volatile("cp.async.ca.shared.global [%0], [%1], 16;" :: "r"(dst), "l"(src))
#define CP_COMMIT()    asm volatile("cp.async.commit_group;" ::: "memory")
#define CP_WAIT(n)     asm volatile("cp.async.wait_group %0;" :: "n"(n) : "memory")

__device__ __forceinline__ void ldm_x4(uint32_t& r0, uint32_t& r1, uint32_t& r2,
                                       uint32_t& r3, uint32_t addr) {
    asm volatile("ldmatrix.sync.aligned.m8n8.x4.shared.b16 {%0,%1,%2,%3}, [%4];"
        : "=r"(r0), "=r"(r1), "=r"(r2), "=r"(r3) : "r"(addr));
}
__device__ __forceinline__ void mma_f16(float* d, const uint32_t* a, const uint32_t* b) {
    asm volatile("mma.sync.aligned.m16n8k16.row.col.f32.f16.f16.f32 "
        "{%0,%1,%2,%3}, {%4,%5,%6,%7}, {%8,%9}, {%0,%1,%2,%3};"
        : "+f"(d[0]), "+f"(d[1]), "+f"(d[2]), "+f"(d[3])
        : "r"(a[0]), "r"(a[1]), "r"(a[2]), "r"(a[3]), "r"(b[0]), "r"(b[1]));
}

// ============================================================
// K0 (merged): block 0: dedup rand_idx; blocks 1..32: query FOFE;
//              blocks 33..: weight fp16 conversion (4 x 512 blocks).
// ============================================================
#define CONV_BLKS 512
__global__ void k_pre(const int* __restrict__ rand_idx,
                      const int* __restrict__ query, const float* __restrict__ emb,
                      const float* __restrict__ Wa, const float* __restrict__ Wb,
                      const float* __restrict__ Wc, const float* __restrict__ Wd) {
    int tid = threadIdx.x;
    int bx  = blockIdx.x;
    if (bx == 0) {
        __shared__ int s_cnt[NSAMP];
        for (int i = tid; i < NSAMP; i += blockDim.x) s_cnt[i] = 0;
        __syncthreads();
        for (int n = tid; n < NEG_N; n += blockDim.x) {
            int s = rand_idx[n];
            s = min(max(s, 0), NSAMP - 1);
            atomicAdd(&s_cnt[s], 1);
        }
        __syncthreads();
        if (tid == 0) {
            int u = 0;
            for (int s = 0; s < NSAMP; s++) {
                if (s_cnt[s] > 0) { g_used[u] = s; g_slot[s] = u + 1; u++; }
                else              { g_slot[s] = 0; }
            }
            g_nused = u;
        }
    } else if (bx <= BATCH) {
        int b = bx - 1;
        __shared__ float qw[LQ];
        __shared__ int   tok[LQ];
        if (tid < LQ) {
            float w = 1.f;
            for (int k = 0; k < LQ - 1 - tid; k++) w *= ALPHA;
            qw[tid]  = w;
            tok[tid] = query[b * LQ + tid];
        }
        __syncthreads();
        for (int e = tid; e < EDIM; e += blockDim.x) {
            float acc = 0.f;
            #pragma unroll 4
            for (int t = 0; t < LQ; t++)
                acc += qw[t] * emb[(size_t)tok[t] * EDIM + e];
            g_qf[b * EDIM + e] = acc;
        }
    } else {
        int cidx  = bx - 1 - BATCH;
        int which = cidx / CONV_BLKS;
        int cb    = cidx % CONV_BLKS;
        const float* W; f16* o; int Mr, K, Kp;
        if      (which == 0) { W = Wa; o = g_W1; Mr = HID;   K = CIN; Kp = KP1; }
        else if (which == 1) { W = Wb; o = g_W2; Mr = HID;   K = HID; Kp = HID; }
        else if (which == 2) { W = Wc; o = g_W3; Mr = HID;   K = HID; Kp = HID; }
        else                 { W = Wd; o = g_W4; Mr = H2DIM; K = HID; Kp = HID; }

        if (K == Kp) {
            int total4 = (Mr * Kp) >> 2;
            for (int v = cb * blockDim.x + tid; v < total4;
                 v += CONV_BLKS * blockDim.x) {
                float4 f = *(const float4*)(W + (size_t)v * 4);
                f16 hv[4] = {__float2half(f.x), __float2half(f.y),
                             __float2half(f.z), __float2half(f.w)};
                *(uint2*)(o + (size_t)v * 4) = *(uint2*)hv;
            }
        } else {
            int total = Mr * Kp;
            for (int idx = cb * blockDim.x + tid; idx < total;
                 idx += CONV_BLKS * blockDim.x) {
                int r = idx / Kp, k = idx - r * Kp;
                float v = (k < K) ? W[(size_t)r * K + k] : 0.f;
                o[idx] = __float2half(v);
            }
        }
    }
}

// ============================================================
// K2: build COMPACT feature matrix (fp16, K padded to KP1)
// ============================================================
__global__ void k_feat(const int* __restrict__ doc, const float* __restrict__ doc_f,
                       const float* __restrict__ emb,
                       const int* __restrict__ target_s, const int* __restrict__ target_e,
                       const int* __restrict__ rand_length, const int* __restrict__ rand_position) {
    int local = blockIdx.x;
    int b     = blockIdx.y;
    int nloc  = 1 + g_nused;
    if (local >= nloc) return;

    __shared__ int   stok[3][16];
    __shared__ int   spos[3][16];
    __shared__ float sw[3][16];
    __shared__ float sdf[3][4];

    int tid = threadIdx.x;

    int base_l, pos_a, ka, base_r;
    if (local == 0) {
        int ts = target_s[b], te = target_e[b];
        base_l = max(ts - 1, 0);
        pos_a  = min(max(te, 0), LD - 1);
        ka     = te - ts;
        base_r = min(te + 1, LD - 1);
    } else {
        int s  = g_used[local - 1];
        int i  = s / PPL, j = s % PPL;
        int rl = min(max(rand_length[i], 0), MWIN - 1);
        int p  = rand_position[i * PPL + j];
        p      = min(max(p, 0), LD - 1);
        pos_a  = p;
        ka     = rl;
        base_l = min(max(p - 1, 0), LD - 1);
        base_r = min(max(p + rl + 1, 0), LD - 1);
    }

    if (tid < 48) {
        int seg = tid >> 4, k = tid & 15;
        float w = 1.f;
        for (int i = 0; i < k; i++) w *= ALPHA;
        int t; bool valid;
        if (seg == 0)      { t = base_l - k; valid = (t >= 0); }
        else if (seg == 1) { t = pos_a - k; valid = (t >= 0) && (k <= ka); }
        else               { t = base_r + k; valid = (t < LD); }
        int tc = min(max(t, 0), LD - 1);
        sw[seg][k]   = valid ? w : 0.f;
        stok[seg][k] = valid ? doc[b * LD + tc] : 0;
        spos[seg][k] = tc;
    }
    __syncthreads();
    if (tid < 12) {
        int seg = tid >> 2, f = tid & 3;
        float acc = 0.f;
        #pragma unroll
        for (int k = 0; k < 16; k++)
            acc += sw[seg][k] * doc_f[((size_t)(b * LD + spos[seg][k])) * NF + f];
        sdf[seg][f] = acc;
    }
    __syncthreads();

    size_t row = (size_t)(b * nloc + local) * KP1;
    for (int c = tid; c < KP1; c += blockDim.x) {
        float acc = 0.f;
        if (c < 3 * DDIM) {
            int seg = (c >= 2 * DDIM) ? 2 : ((c >= DDIM) ? 1 : 0);
            int ch = c - seg * DDIM;
            if (ch < EDIM) {
                #pragma unroll
                for (int k = 0; k < 16; k++)
                    acc += sw[seg][k] * emb[(size_t)stok[seg][k] * EDIM + ch];
            } else {
                acc = sdf[seg][ch - EDIM];
            }
        } else if (c < CIN) {
            acc = g_qf[b * EDIM + (c - 3 * DDIM)];
        }
        g_F[row + c] = __float2half(acc);
    }
}

// ============================================================
// K3: fp16 HMMA GEMM (CTA 64x64, 4 warps 2Mx2N, warp 32x32,
//   3-stage cp.async, 48KB, 4 CTAs/SM). KSPLIT: 2-way K halves ->
//   fp16 partials g_part. !KSPLIT (layer 4): fused W5-dot -> g_dotp.
// ============================================================
#define OFF_A 0
#define OFF_B 8192
#define STAGE_BYTES 16384
#define NSTAGE 3
#define SMEM_TOT (NSTAGE*STAGE_BYTES)   // 49152

__device__ __forceinline__ void load_tile_cp(const f16* __restrict__ G, int row0,
                                             int stride, int k0, uint32_t smd, int tid) {
    #pragma unroll
    for (int it = 0; it < 4; it++) {
        int v = tid + it * 128;
        int r = v >> 3, seg = v & 7;
        const f16* src = G + (size_t)(row0 + r) * stride + k0 + seg * 8;
        CP16(smd + SWZ(r * 128 + seg * 16), src);
    }
}

template<bool KSPLIT>
__global__ __launch_bounds__(128, 4)
void k_tgemm(const f16* __restrict__ A, const f16* __restrict__ B,
             const float* __restrict__ W5, int Mdim, int K) {
    int ncols = BATCH * (1 + g_nused);
    int n0 = blockIdx.y * NTILE;
    if (n0 >= ncols) return;
    int seg  = KSPLIT ? (blockIdx.x & 1) : 0;
    int mblk = KSPLIT ? (blockIdx.x >> 1) : blockIdx.x;
    int m0 = mblk * 64;

    int nch_tot = K >> 6;
    int c0, c1;
    if (KSPLIT) {
        int half = nch_tot >> 1;
        c0 = seg ? half : 0;
        c1 = seg ? nch_tot : half;
    } else { c0 = 0; c1 = nch_tot; }

    extern __shared__ __align__(128) char sm[];
    uint32_t smb = smem_u32(sm);
    int tid  = threadIdx.x;
    int wid  = tid >> 5, lane = tid & 31;
    int wm   = wid & 1;
    int wn   = wid >> 1;

    int a_row_l = lane & 15;
    int a_off_l = (lane >> 4) << 4;
    int b_n_l   = ((lane >> 4) << 3) + (lane & 7);
    int b_off_l = ((lane >> 3) & 1) << 4;

    float acc[2][4][4];
    #pragma unroll
    for (int i = 0; i < 2; i++)
        #pragma unroll
        for (int j = 0; j < 4; j++)
            #pragma unroll
            for (int q = 0; q < 4; q++) acc[i][j][q] = 0.f;

    #pragma unroll
    for (int p = 0; p < 2; p++) {
        if (c0 + p < c1) {
            uint32_t sb = smb + p * STAGE_BYTES;
            load_tile_cp(A, m0, K, (c0 + p) << 6, sb + OFF_A, tid);
            load_tile_cp(B, n0, K, (c0 + p) << 6, sb + OFF_B, tid);
            CP_COMMIT();
        }
    }

    for (int c = c0; c < c1; c++) {
        if (c + 2 < c1) {
            uint32_t sb = smb + ((c - c0 + 2) % NSTAGE) * STAGE_BYTES;
            int k0 = (c + 2) << 6;
            load_tile_cp(A, m0, K, k0, sb + OFF_A, tid);
            load_tile_cp(B, n0, K, k0, sb + OFF_B, tid);
            CP_COMMIT();
            CP_WAIT(2);
        } else if (c + 1 < c1) {
            CP_WAIT(1);
        } else {
            CP_WAIT(0);
        }
        __syncthreads();

        uint32_t sb = smb + ((c - c0) % NSTAGE) * STAGE_BYTES;
        #pragma unroll
        for (int kk = 0; kk < 4; kk++) {
            int kb = kk << 5;
            uint32_t af[2][4], bf[2][4];
            #pragma unroll
            for (int ma = 0; ma < 2; ma++) {
                uint32_t off = SWZ((wm * 32 + ma * 16 + a_row_l) * 128 + kb + a_off_l);
                ldm_x4(af[ma][0], af[ma][1], af[ma][2], af[ma][3], sb + OFF_A + off);
            }
            #pragma unroll
            for (int nb = 0; nb < 2; nb++) {
                uint32_t off = SWZ((wn * 32 + nb * 16 + b_n_l) * 128 + kb + b_off_l);
                ldm_x4(bf[nb][0], bf[nb][1], bf[nb][2], bf[nb][3], sb + OFF_B + off);
            }
            #pragma unroll
            for (int ma = 0; ma < 2; ma++) {
                #pragma unroll
                for (int na = 0; na < 4; na++) {
                    mma_f16(acc[ma][na], af[ma], &bf[na >> 1][(na & 1) * 2]);
                }
            }
        }
        __syncthreads();
    }

    if (KSPLIT) {
        f16* P = g_part + (size_t)seg * NCOLP * HID;
        #pragma unroll
        for (int ma = 0; ma < 2; ma++) {
            int mrow = m0 + wm * 32 + ma * 16 + (lane >> 2);
            #pragma unroll
            for (int na = 0; na < 4; na++) {
                int nb2 = n0 + wn * 32 + na * 8 + ((lane & 3) << 1);
                #pragma unroll
                for (int q = 0; q < 4; q++) {
                    int n = nb2 + (q & 1);
                    int m = mrow + ((q >> 1) << 3);
                    if (n < ncols)
                        P[(size_t)n * Mdim + m] = __float2half(acc[ma][na][q]);
                }
            }
        }
    } else {
        __shared__ float sdot[NTILE];
        for (int i = tid; i < NTILE; i += 128) sdot[i] = 0.f;
        __syncthreads();
        #pragma unroll
        for (int na = 0; na < 4; na++) {
            float p0 = 0.f, p1 = 0.f;
            #pragma unroll
            for (int ma = 0; ma < 2; ma++) {
                int mb = m0 + wm * 32 + ma * 16 + (lane >> 2);
                float w5a = W5[mb], w5b = W5[mb + 8];
                p0 += fmaxf(acc[ma][na][0], 0.f) * w5a + fmaxf(acc[ma][na][2], 0.f) * w5b;
                p1 += fmaxf(acc[ma][na][1], 0.f) * w5a + fmaxf(acc[ma][na][3], 0.f) * w5b;
            }
            int ni = wn * 32 + na * 8 + ((lane & 3) << 1);
            atomicAdd(&sdot[ni], p0);
            atomicAdd(&sdot[ni + 1], p1);
        }
        __syncthreads();
        for (int i = tid; i < NTILE; i += 128) {
            int n = n0 + i;
            if (n < ncols) g_dotp[mblk * NCOLP + n] = sdot[i];
        }
    }
}

// ============================================================
// K3b: sum 2 fp16 K-split partials + ReLU + fp16 convert
// ============================================================
__global__ void k_act(f16* __restrict__ O) {
    int ncols = BATCH * (1 + g_nused);
    int total8 = (ncols * HID) >> 3;       // 16B vectors of 8 halves
    const f16* P0 = g_part;
    const f16* P1 = g_part + (size_t)NCOLP * HID;
    for (int v = blockIdx.x * blockDim.x + threadIdx.x; v < total8;
         v += gridDim.x * blockDim.x) {
        size_t base = (size_t)v * 8;
        uint4 ua = *(const uint4*)(P0 + base);
        uint4 ub = *(const uint4*)(P1 + base);
        const __half2* ha = (const __half2*)&ua;
        const __half2* hb = (const __half2*)&ub;
        __half2 r[4];
        #pragma unroll
        for (int i = 0; i < 4; i++) {
            float2 fa = __half22float2(ha[i]);
            float2 fb = __half22float2(hb[i]);
            r[i] = __floats2half2_rn(fmaxf(fa.x + fb.x, 0.f),
                                     fmaxf(fa.y + fb.y, 0.f));
        }
        *(uint4*)(O + base) = *(uint4*)r;
    }
}

// ============================================================
// K5: sigmoid + loss (permutation-invariant; perm_idx drops out)
// ============================================================
__global__ void k_loss(const int* __restrict__ rand_idx, float* __restrict__ out) {
    int tid = threadIdx.x;
    int nloc = 1 + g_nused;
    int ncols = BATCH * nloc;
    for (int c = tid; c < ncols; c += 256) {
        float d = 0.f;
        #pragma unroll
        for (int p = 0; p < MB4; p++) d += g_dotp[p * NCOLP + c];
        g_score[c] = 1.f / (1.f + expf(-d));
    }
    __syncthreads();
    float acc = 0.f;
    for (int idx = tid; idx < BATCH * NEG_N; idx += 256) {
        int b = idx >> 7, n = idx & 127;
        int s = rand_idx[n];
        s = min(max(s, 0), NSAMP - 1);
        int u = g_slot[s];
        float v = g_score[b * nloc + u];
        acc += v * v;
    }
    if (tid < BATCH) {
        float v = g_score[tid * nloc] - 1.f;
        acc += 128.f * v * v;
    }
    __shared__ float sh[256];
    sh[tid] = acc;
    __syncthreads();
    for (int o = 128; o; o >>= 1) {
        if (tid < o) sh[tid] += sh[tid + o];
        __syncthreads();
    }
    if (tid == 0) out[0] = sh[0];
}

// ============================================================
// launch
// ============================================================
extern "C" void kernel_launch(void* const* d_in, const int* in_sizes, int n_in,
                              void* d_out, int out_size) {
    const int*   doc       = (const int*)  d_in[0];
    const float* doc_f     = (const float*)d_in[1];
    const int*   query     = (const int*)  d_in[2];
    const int*   target_s  = (const int*)  d_in[3];
    const int*   target_e  = (const int*)  d_in[4];
    const float* emb       = (const float*)d_in[7];
    const float* W1        = (const float*)d_in[8];
    const float* W2        = (const float*)d_in[9];
    const float* W3        = (const float*)d_in[10];
    const float* W4        = (const float*)d_in[11];
    const float* W5        = (const float*)d_in[12];
    const int*   rand_len  = (const int*)  d_in[13];
    const int*   rand_pos  = (const int*)  d_in[14];
    const int*   rand_idx  = (const int*)  d_in[15];
    float* out = (float*)d_out;

    f16 *W1p,*W2p,*W3p,*W4p,*F,*H1,*H2,*H3;
    cudaGetSymbolAddress((void**)&W1p, g_W1);
    cudaGetSymbolAddress((void**)&W2p, g_W2);
    cudaGetSymbolAddress((void**)&W3p, g_W3);
    cudaGetSymbolAddress((void**)&W4p, g_W4);
    cudaGetSymbolAddress((void**)&F,   g_F);
    cudaGetSymbolAddress((void**)&H1,  g_H1);
    cudaGetSymbolAddress((void**)&H2,  g_H2);
    cudaGetSymbolAddress((void**)&H3,  g_H3);

    cudaFuncSetAttribute(k_tgemm<true>,  cudaFuncAttributeMaxDynamicSharedMemorySize, SMEM_TOT);
    cudaFuncSetAttribute(k_tgemm<false>, cudaFuncAttributeMaxDynamicSharedMemorySize, SMEM_TOT);

    // merged: dedup + query-FOFE + weight conversion (independent phases)
    k_pre<<<1 + BATCH + 4 * CONV_BLKS, 256>>>(rand_idx, query, emb, W1, W2, W3, W4);
    {
        dim3 g(NLOC, BATCH);
        k_feat<<<g, 256>>>(doc, doc_f, emb, target_s, target_e, rand_len, rand_pos);
    }
    {
        dim3 gs(2 * HID / 64, NTILES);   // K-split layers 1-3
        dim3 g4(H2DIM / 64,   NTILES);   // fused final layer
        k_tgemm<true ><<<gs, 128, SMEM_TOT>>>(W1p, F,  (const float*)0, HID, KP1);
        k_act<<<592, 256>>>(H1);
        k_tgemm<true ><<<gs, 128, SMEM_TOT>>>(W2p, H1, (const float*)0, HID, HID);
        k_act<<<592, 256>>>(H2);
        k_tgemm<true ><<<gs, 128, SMEM_TOT>>>(W3p, H2, (const float*)0, HID, HID);
        k_act<<<592, 256>>>(H3);
        k_tgemm<false><<<g4, 128, SMEM_TOT>>>(W4p, H3, W5, H2DIM, HID);
    }
    k_loss<<<1, 256>>>(rand_idx, out);
}